// round 14
// baseline (speedup 1.0000x reference)
#include <cuda_runtime.h>
#include <cuda_bf16.h>

// DCN cross network, fused, affine-span form:
//   t_l = x0.w_l (4 dots), beta_l = B_l.w_l (row-indep), gamma recurrence,
//   out = gamma4*x0 + Bsum.
// R13 == R12 (infra failure last round, re-bench): R10 compute body was
// within ~15% of HBM floor but lost ~15% to 3.46-wave quantization.
//  - persistent grid: 592 CTAs x 128 thr = exactly 4 CTAs/SM on 148 SMs
//  - WARP-level dynamic work stealing over 8192 row-pairs via one global
//    atomic counter; next index grabbed an iteration early (latency hidden)
//  - pair-per-warp, shared W LDS, packed f32x2, value-halving reduce,
//    register-resident Bsum slice.

#define B_ROWS   16384
#define N_PAIRS  (B_ROWS / 2)
#define THREADS  128
#define WARPS    4
#define GRID     592                   // 148 SMs x 4 CTAs
#define NWARPS_TOTAL (GRID * WARPS)    // 2368
#define VPR      256                   // 16B vectors per row

typedef unsigned long long u64;

__device__ unsigned g_ctr;

__global__ void reset_ctr_kernel() { g_ctr = NWARPS_TOTAL; }

__device__ __forceinline__ u64 fma2(u64 a, u64 b, u64 c) {
    u64 d; asm("fma.rn.f32x2 %0, %1, %2, %3;" : "=l"(d) : "l"(a), "l"(b), "l"(c)); return d;
}
__device__ __forceinline__ u64 mul2(u64 a, u64 b) {
    u64 d; asm("mul.rn.f32x2 %0, %1, %2;" : "=l"(d) : "l"(a), "l"(b)); return d;
}
__device__ __forceinline__ u64 add2(u64 a, u64 b) {
    u64 d; asm("add.rn.f32x2 %0, %1, %2;" : "=l"(d) : "l"(a), "l"(b)); return d;
}
__device__ __forceinline__ float hsum2(u64 p) {
    float lo, hi; asm("mov.b64 {%0, %1}, %2;" : "=f"(lo), "=f"(hi) : "l"(p)); return lo + hi;
}
__device__ __forceinline__ u64 pack2(float s) {
    u64 d; asm("mov.b64 %0, {%1, %1};" : "=l"(d) : "f"(s)); return d;
}
__device__ __forceinline__ ulonglong2 addv(ulonglong2 a, ulonglong2 b) {
    ulonglong2 r; r.x = add2(a.x, b.x); r.y = add2(a.y, b.y); return r;
}
__device__ __forceinline__ float dotv(ulonglong2 a, ulonglong2 b) {
    return hsum2(fma2(a.y, b.y, mul2(a.x, b.x)));
}

// reduce 4 values over the warp; returns (t0,t1,t2,t3) on all lanes. 10 SHFL.
__device__ __forceinline__ float4 wreduce4(float V0, float V1, float V2, float V3,
                                           int lane) {
    const bool hi16 = (lane & 16);
    float k0 = hi16 ? V2 : V0, g0 = hi16 ? V0 : V2;
    float k1 = hi16 ? V3 : V1, g1 = hi16 ? V1 : V3;
    float U0 = k0 + __shfl_xor_sync(0xffffffffu, g0, 16);
    float U1 = k1 + __shfl_xor_sync(0xffffffffu, g1, 16);
    const bool hi8 = (lane & 8);
    float k = hi8 ? U1 : U0, g = hi8 ? U0 : U1;
    float V = k + __shfl_xor_sync(0xffffffffu, g, 8);
    V += __shfl_xor_sync(0xffffffffu, V, 4);
    V += __shfl_xor_sync(0xffffffffu, V, 2);
    V += __shfl_xor_sync(0xffffffffu, V, 1);
    return make_float4(__shfl_sync(0xffffffffu, V, 0),
                       __shfl_sync(0xffffffffu, V, 8),
                       __shfl_sync(0xffffffffu, V, 16),
                       __shfl_sync(0xffffffffu, V, 24));
}

__global__ __launch_bounds__(THREADS, 4)
void dcn_cross_kernel(const ulonglong2* __restrict__ x,
                      const ulonglong2* __restrict__ w,
                      const ulonglong2* __restrict__ b,
                      ulonglong2* __restrict__ out) {
    const int t    = threadIdx.x;
    const int lane = t & 31;
    const int wid  = t >> 5;

    __shared__ __align__(16) ulonglong2 sw[4][VPR];   // weights, 16KB
    __shared__ __align__(16) ulonglong2 sbsum[VPR];   // Bsum, 4KB
    __shared__ __align__(16) float4 sbeta[WARPS];

    // ---- prologue: stage W, compute Bsum + beta scalars ----
    {
        #pragma unroll
        for (int half = 0; half < 2; half++) {
            const int i = t + half * THREADS;
            sw[0][i] = w[0 * VPR + i];
            sw[1][i] = w[1 * VPR + i];
            sw[2][i] = w[2 * VPR + i];
            sw[3][i] = w[3 * VPR + i];
        }
        float p1 = 0.f, p2 = 0.f, p3 = 0.f;
        #pragma unroll
        for (int half = 0; half < 2; half++) {
            const int i = t + half * THREADS;
            ulonglong2 B = b[0 * VPR + i];                  // B1
            p1 += dotv(B, sw[1][i]);
            B = addv(B, b[1 * VPR + i]);                    // B2
            p2 += dotv(B, sw[2][i]);
            B = addv(B, b[2 * VPR + i]);                    // B3
            p3 += dotv(B, sw[3][i]);
            B = addv(B, b[3 * VPR + i]);                    // Bsum
            sbsum[i] = B;
        }
        #pragma unroll
        for (int o = 16; o > 0; o >>= 1) {
            p1 += __shfl_down_sync(0xffffffffu, p1, o);
            p2 += __shfl_down_sync(0xffffffffu, p2, o);
            p3 += __shfl_down_sync(0xffffffffu, p3, o);
        }
        if (lane == 0) sbeta[wid] = make_float4(p1, p2, p3, 0.f);
    }
    __syncthreads();

    float beta1 = 0.f, beta2 = 0.f, beta3 = 0.f;
    #pragma unroll
    for (int k = 0; k < WARPS; k++) {
        const float4 v = sbeta[k];
        beta1 += v.x; beta2 += v.y; beta3 += v.z;
    }

    // Bsum lane-slice into registers (reused for every pair)
    ulonglong2 Bs[8];
    #pragma unroll
    for (int v = 0; v < 8; v++) Bs[v] = sbsum[v * 32 + lane];

    // ---- dynamic warp-level work stealing over row pairs ----
    unsigned cur = blockIdx.x * WARPS + wid;   // pre-assigned first pair

    #pragma unroll 1
    while (cur < N_PAIRS) {
        // grab next task NOW; ATOMG latency hidden behind this pair's work
        unsigned nxt;
        if (lane == 0) nxt = atomicAdd(&g_ctr, 1u);
        nxt = __shfl_sync(0xffffffffu, nxt, 0);

        const size_t rowA = (size_t)cur * 2;
        const ulonglong2* xpA = x + rowA * VPR;
        const ulonglong2* xpB = xpA + VPR;
        ulonglong2* opA       = out + rowA * VPR;
        ulonglong2* opB       = opA + VPR;

        ulonglong2 xA[8], xB[8];
        #pragma unroll
        for (int v = 0; v < 8; v++) xA[v] = __ldcs(&xpA[v * 32 + lane]);
        #pragma unroll
        for (int v = 0; v < 8; v++) xB[v] = __ldcs(&xpB[v * 32 + lane]);

        // dots: one W LDS serves both rows
        u64 aA[4], aB[4];
        #pragma unroll
        for (int l = 0; l < 4; l++) {
            const ulonglong2 wv = sw[l][lane];
            aA[l] = fma2(xA[0].y, wv.y, mul2(xA[0].x, wv.x));
            aB[l] = fma2(xB[0].y, wv.y, mul2(xB[0].x, wv.x));
        }
        #pragma unroll
        for (int v = 1; v < 8; v++) {
            #pragma unroll
            for (int l = 0; l < 4; l++) {
                const ulonglong2 wv = sw[l][v * 32 + lane];
                aA[l] = fma2(xA[v].x, wv.x, aA[l]);
                aA[l] = fma2(xA[v].y, wv.y, aA[l]);
                aB[l] = fma2(xB[v].x, wv.x, aB[l]);
                aB[l] = fma2(xB[v].y, wv.y, aB[l]);
            }
        }

        const float4 tA = wreduce4(hsum2(aA[0]), hsum2(aA[1]),
                                   hsum2(aA[2]), hsum2(aA[3]), lane);
        const float4 tB = wreduce4(hsum2(aB[0]), hsum2(aB[1]),
                                   hsum2(aB[2]), hsum2(aB[3]), lane);

        float gA = 1.f + tA.x;
        gA = fmaf(gA, tA.y, gA + beta1);
        gA = fmaf(gA, tA.z, gA + beta2);
        gA = fmaf(gA, tA.w, gA + beta3);
        float gB = 1.f + tB.x;
        gB = fmaf(gB, tB.y, gB + beta1);
        gB = fmaf(gB, tB.z, gB + beta2);
        gB = fmaf(gB, tB.w, gB + beta3);

        const u64 gpA = pack2(gA), gpB = pack2(gB);

        #pragma unroll
        for (int v = 0; v < 8; v++) {
            ulonglong2 oa, ob;
            oa.x = fma2(xA[v].x, gpA, Bs[v].x);
            oa.y = fma2(xA[v].y, gpA, Bs[v].y);
            ob.x = fma2(xB[v].x, gpB, Bs[v].x);
            ob.y = fma2(xB[v].y, gpB, Bs[v].y);
            __stcs(&opA[v * 32 + lane], oa);
            __stcs(&opB[v * 32 + lane], ob);
        }

        cur = nxt;
    }
}

extern "C" void kernel_launch(void* const* d_in, const int* in_sizes, int n_in,
                              void* d_out, int out_size) {
    const ulonglong2* x = (const ulonglong2*)d_in[0];
    const ulonglong2* w = (const ulonglong2*)d_in[1];
    const ulonglong2* b = (const ulonglong2*)d_in[2];
    ulonglong2* o = (ulonglong2*)d_out;
    reset_ctr_kernel<<<1, 1>>>();
    dcn_cross_kernel<<<GRID, THREADS>>>(x, w, b, o);
}